// round 11
// baseline (speedup 1.0000x reference)
#include <cuda_runtime.h>
#include <cuda_bf16.h>

#define N_COLS 2048                 // hidden dim
#define VECS_PER_ROW (N_COLS / 4)   // 512 float4
#define THREADS 256                 // 2 float4 per thread
#define NWARPS (THREADS / 32)
#define EPS 1e-5f

// Best measured configuration (R7): 35.94us kernel, 7.46 TB/s effective
// (93% of HBM spec). RMSNorm over [16384, 2048] fp32 is HBM-turnaround-bound;
// verified plateau across occ 27-89%, MLP 2-16, persistent/pipelined variants.

__global__ __launch_bounds__(THREADS)
void rmsnorm_kernel(const float4* __restrict__ x,
                    const float4* __restrict__ g,
                    float4* __restrict__ out)
{
    const int row = blockIdx.x;
    const float4* xr = x + (size_t)row * VECS_PER_ROW;
    float4* outr = out + (size_t)row * VECS_PER_ROW;

    const int t = threadIdx.x;
    const int warp = t >> 5;
    const int lane = t & 31;

    // x has zero reuse within a launch: bypass L1 fill (L2-only).
    float4 v0 = __ldcg(&xr[t]);
    float4 v1 = __ldcg(&xr[t + THREADS]);

    float ss = v0.x * v0.x + v0.y * v0.y + v0.z * v0.z + v0.w * v0.w
             + v1.x * v1.x + v1.y * v1.y + v1.z * v1.z + v1.w * v1.w;

    // Warp reduce (redux.sync.add.f32 is NOT supported on sm_103).
    #pragma unroll
    for (int off = 16; off > 0; off >>= 1)
        ss += __shfl_xor_sync(0xFFFFFFFFu, ss, off);

    // Single-barrier block reduce: publish 8 warp partials, then every
    // thread sums all 8 from smem (broadcast reads, no second barrier,
    // no serialized warp0 chain).
    __shared__ float warp_sums[NWARPS];
    if (lane == 0) warp_sums[warp] = ss;
    __syncthreads();

    float total = 0.0f;
    #pragma unroll
    for (int w = 0; w < NWARPS; w++)
        total += warp_sums[w];

    const float scale = rsqrtf(total * (1.0f / (float)N_COLS) + EPS);

    // g: 8 KB, broadcast across all rows — default policy, L1/L2-resident.
    float4 g0 = g[t];
    float4 g1 = g[t + THREADS];

    float4 o0, o1;
    o0.x = v0.x * scale * g0.x;
    o0.y = v0.y * scale * g0.y;
    o0.z = v0.z * scale * g0.z;
    o0.w = v0.w * scale * g0.w;
    o1.x = v1.x * scale * g1.x;
    o1.y = v1.y * scale * g1.y;
    o1.z = v1.z * scale * g1.z;
    o1.w = v1.w * scale * g1.w;

    outr[t] = o0;
    outr[t + THREADS] = o1;
}

extern "C" void kernel_launch(void* const* d_in, const int* in_sizes, int n_in,
                              void* d_out, int out_size)
{
    const float4* x = (const float4*)d_in[0];
    const float4* g = (const float4*)d_in[1];
    float4* out = (float4*)d_out;

    const int n_rows = in_sizes[0] / N_COLS;  // 16384

    rmsnorm_kernel<<<n_rows, THREADS>>>(x, g, out);
}

// round 12
// speedup vs baseline: 1.0007x; 1.0007x over previous
#include <cuda_runtime.h>
#include <cuda_bf16.h>

#define N_COLS 2048                 // hidden dim
#define VECS_PER_ROW (N_COLS / 4)   // 512 float4
#define THREADS 256                 // 2 float4 per thread
#define NWARPS (THREADS / 32)
#define EPS 1e-5f

// R7 structure (best measured: 35.94us kernel, 7.46 TB/s effective, 93% of
// HBM spec) + final single-variable probe: write-through stores (__stwt)
// to skip L2 write-allocation for the 128 MB output stream.

__global__ __launch_bounds__(THREADS)
void rmsnorm_kernel(const float4* __restrict__ x,
                    const float4* __restrict__ g,
                    float4* __restrict__ out)
{
    const int row = blockIdx.x;
    const float4* xr = x + (size_t)row * VECS_PER_ROW;
    float4* outr = out + (size_t)row * VECS_PER_ROW;

    const int t = threadIdx.x;
    const int warp = t >> 5;
    const int lane = t & 31;

    // x has zero reuse within a launch: bypass L1 fill (L2-only).
    float4 v0 = __ldcg(&xr[t]);
    float4 v1 = __ldcg(&xr[t + THREADS]);

    float ss = v0.x * v0.x + v0.y * v0.y + v0.z * v0.z + v0.w * v0.w
             + v1.x * v1.x + v1.y * v1.y + v1.z * v1.z + v1.w * v1.w;

    // Warp reduce (redux.sync.add.f32 is NOT supported on sm_103).
    #pragma unroll
    for (int off = 16; off > 0; off >>= 1)
        ss += __shfl_xor_sync(0xFFFFFFFFu, ss, off);

    // Single-barrier block reduce: publish 8 warp partials, then every
    // thread sums all 8 from smem (broadcast reads, no second barrier).
    __shared__ float warp_sums[NWARPS];
    if (lane == 0) warp_sums[warp] = ss;
    __syncthreads();

    float total = 0.0f;
    #pragma unroll
    for (int w = 0; w < NWARPS; w++)
        total += warp_sums[w];

    const float scale = rsqrtf(total * (1.0f / (float)N_COLS) + EPS);

    // g: 8 KB, broadcast across all rows — default policy, L1/L2-resident.
    float4 g0 = g[t];
    float4 g1 = g[t + THREADS];

    float4 o0, o1;
    o0.x = v0.x * scale * g0.x;
    o0.y = v0.y * scale * g0.y;
    o0.z = v0.z * scale * g0.z;
    o0.w = v0.w * scale * g0.w;
    o1.x = v1.x * scale * g1.x;
    o1.y = v1.y * scale * g1.y;
    o1.z = v1.z * scale * g1.z;
    o1.w = v1.w * scale * g1.w;

    // Write-through stores: output is never re-read; don't allocate in L2.
    __stwt(&outr[t], o0);
    __stwt(&outr[t + THREADS], o1);
}

extern "C" void kernel_launch(void* const* d_in, const int* in_sizes, int n_in,
                              void* d_out, int out_size)
{
    const float4* x = (const float4*)d_in[0];
    const float4* g = (const float4*)d_in[1];
    float4* out = (float4*)d_out;

    const int n_rows = in_sizes[0] / N_COLS;  // 16384

    rmsnorm_kernel<<<n_rows, THREADS>>>(x, g, out);
}